// round 5
// baseline (speedup 1.0000x reference)
#include <cuda_runtime.h>

#define BB 16384
#define CC 8192
#define NUM_TAIL 16
#define NTHREADS 512
#define VEC_PER_THREAD 4   // 8192 floats / 4 (float4) / 512 threads

// Scratch (no cudaMalloc allowed) — device globals. Static-zero initialized;
// the last CTA re-zeroes g_counts / g_arrive so every graph replay starts clean.
__device__ int      g_counts[CC];
__device__ float    g_pen[BB];       // per-row base penalty (weight 1)
__device__ unsigned g_arrive;        // CTA arrival counter (last-block pattern)

__device__ __forceinline__ int clamp_lab(int lab) {
    lab = lab < 0 ? 0 : lab;
    return lab >= CC ? CC - 1 : lab;
}

// Single persistent-dependency kernel:
//  Phase 1 (all 16384 CTAs): one CTA per row, streaming max/argmax + exp-sum in
//    a single HBM pass; emit argmax count + base focal penalty.
//  Phase 2 (last CTA to arrive): weighted sum over all rows, deterministic tree.
__global__ __launch_bounds__(NTHREADS) void fused_kernel(
    const float* __restrict__ x, const int* __restrict__ labels,
    const int* __restrict__ prev, float* __restrict__ out)
{
    const int row = blockIdx.x;
    const int t   = threadIdx.x;
    const float4* xr = reinterpret_cast<const float4*>(x + (size_t)row * CC);

    const int lab = clamp_lab(labels[row]);

    // Load this thread's 16 elements into registers (4 x LDG.128).
    float4 v[VEC_PER_THREAD];
#pragma unroll
    for (int i = 0; i < VEC_PER_THREAD; i++)
        v[i] = xr[i * NTHREADS + t];

    __shared__ float s_xtrue;
    // The thread owning column `lab` publishes x_true from registers.
    {
        int lv = lab >> 2;                 // float4 index
        int owner_t = lv & (NTHREADS - 1);
        int owner_i = lv >> 9;             // / NTHREADS
        if (t == owner_t) {
            float4 vv = v[owner_i];
            int c = lab & 3;
            s_xtrue = (c == 0) ? vv.x : (c == 1) ? vv.y : (c == 2) ? vv.z : vv.w;
        }
    }

    // Local max + argmax (first occurrence: columns ascend in i then j for fixed t).
    float m = -3.4e38f;
    int   idx = 0x7fffffff;
#pragma unroll
    for (int i = 0; i < VEC_PER_THREAD; i++) {
        int base = (i * NTHREADS + t) * 4;
        if (v[i].x > m) { m = v[i].x; idx = base;     }
        if (v[i].y > m) { m = v[i].y; idx = base + 1; }
        if (v[i].z > m) { m = v[i].z; idx = base + 2; }
        if (v[i].w > m) { m = v[i].w; idx = base + 3; }
    }

    // Local exp-sum against local max.
    float s = 0.f;
#pragma unroll
    for (int i = 0; i < VEC_PER_THREAD; i++) {
        s += __expf(v[i].x - m);
        s += __expf(v[i].y - m);
        s += __expf(v[i].z - m);
        s += __expf(v[i].w - m);
    }

    // Warp butterfly merge of (m, s, idx) with first-index tie-break.
#pragma unroll
    for (int off = 16; off > 0; off >>= 1) {
        float m2 = __shfl_xor_sync(0xffffffffu, m, off);
        float s2 = __shfl_xor_sync(0xffffffffu, s, off);
        int   i2 = __shfl_xor_sync(0xffffffffu, idx, off);
        float M  = fmaxf(m, m2);
        s = s * __expf(m - M) + s2 * __expf(m2 - M);
        if (m2 > m || (m2 == m && i2 < idx)) idx = i2;
        m = M;
    }

    // Cross-warp merge (16 warps) via shared memory; warp 0 finishes.
    __shared__ float sm[16], ss[16];
    __shared__ int   si[16];
    const int warp = t >> 5, lane = t & 31;
    if (lane == 0) { sm[warp] = m; ss[warp] = s; si[warp] = idx; }
    __syncthreads();

    __shared__ bool s_last;
    if (warp == 0) {
        m   = (lane < 16) ? sm[lane] : -3.4e38f;
        s   = (lane < 16) ? ss[lane] : 0.f;
        idx = (lane < 16) ? si[lane] : 0x7fffffff;
#pragma unroll
        for (int off = 16; off > 0; off >>= 1) {
            float m2 = __shfl_xor_sync(0xffffffffu, m, off);
            float s2 = __shfl_xor_sync(0xffffffffu, s, off);
            int   i2 = __shfl_xor_sync(0xffffffffu, idx, off);
            float M  = fmaxf(m, m2);
            s = s * __expf(m - M) + s2 * __expf(m2 - M);
            if (m2 > m || (m2 == m && i2 < idx)) idx = i2;
            m = M;
        }
        if (lane == 0) {
            float lse = m + __logf(s);
            float p   = __expf(s_xtrue - lse);           // softmax prob of true class
            g_pen[row] = -__logf(p + 1e-7f) * (1.f - p); // base penalty (w=1)
            atomicAdd(&g_counts[idx], 1);
            __threadfence();
            unsigned rank = atomicAdd(&g_arrive, 1u);
            s_last = (rank == (unsigned)(BB - 1));
        }
    }
    __syncthreads();
    if (!s_last) return;

    // ---- Phase 2: last CTA reduces all rows (deterministic, fixed order) ----
    float acc = 0.f;
    const int4* lab4 = reinterpret_cast<const int4*>(labels);
    const float4* pen4 = reinterpret_cast<const float4*>(g_pen);
    for (int i = t; i < BB / 4; i += NTHREADS) {
        float4 p4 = __ldcg(&pen4[i]);
        int4   l4 = lab4[i];
        int labs[4] = {l4.x, l4.y, l4.z, l4.w};
        float pens[4] = {p4.x, p4.y, p4.z, p4.w};
#pragma unroll
        for (int k = 0; k < 4; k++) {
            int lb = clamp_lab(labs[k]);
            float w = 1.f;
            if (lb >= CC - NUM_TAIL) {
                int pv = prev[lb];
                int cu = __ldcg(&g_counts[lb]);
                if      (pv > 0 && cu < pv) w = 4.f;
                else if (pv > 0 && cu > pv) w = 2.f;
                else                        w = 3.f;
            }
            acc += pens[k] * w;
        }
    }
#pragma unroll
    for (int off = 16; off > 0; off >>= 1)
        acc += __shfl_xor_sync(0xffffffffu, acc, off);
    __shared__ float red[16];
    if (lane == 0) red[warp] = acc;
    __syncthreads();   // also orders all g_counts reads before the re-zero below

    // Reset scratch for the next graph replay.
    for (int i = t; i < CC; i += NTHREADS) g_counts[i] = 0;

    if (warp == 0) {
        acc = (lane < 16) ? red[lane] : 0.f;
#pragma unroll
        for (int off = 16; off > 0; off >>= 1)
            acc += __shfl_xor_sync(0xffffffffu, acc, off);
        if (lane == 0) {
            out[0] = acc * (0.1f / (float)BB);
            g_arrive = 0u;
        }
    }
}

extern "C" void kernel_launch(void* const* d_in, const int* in_sizes, int n_in,
                              void* d_out, int out_size)
{
    const float* x      = (const float*)d_in[0];
    const int*   labels = (const int*)d_in[1];
    const int*   prev   = (const int*)d_in[2];
    float*       out    = (float*)d_out;

    fused_kernel<<<BB, NTHREADS>>>(x, labels, prev, out);
}

// round 6
// speedup vs baseline: 1.3699x; 1.3699x over previous
#include <cuda_runtime.h>

#define BB 16384
#define CC 8192
#define NUM_TAIL 16
#define NTHREADS 512
#define VEC_PER_THREAD 4   // 8192 floats / 4 (float4) / 512 threads

// Scratch (no cudaMalloc allowed) — device globals. Static-zero initialized;
// finalize_kernel re-zeroes g_counts after use so every graph replay starts clean.
__device__ int   g_counts[CC];
__device__ float g_pen[BB];   // per-row base focal penalty (weight 1)

__device__ __forceinline__ int clamp_lab(int lab) {
    lab = lab < 0 ? 0 : lab;
    return lab >= CC ? CC - 1 : lab;
}

// One CTA per row: streaming max/argmax + exp-sum in a single HBM pass.
// Epilogue computes the base focal penalty for the row (exp/log on idle pipes).
__global__ __launch_bounds__(NTHREADS) void row_kernel(
    const float* __restrict__ x, const int* __restrict__ labels)
{
    const int row = blockIdx.x;
    const int t   = threadIdx.x;
    const float4* xr = reinterpret_cast<const float4*>(x + (size_t)row * CC);

    const int lab = clamp_lab(labels[row]);

    // Load this thread's 16 elements into registers (4 x LDG.128).
    float4 v[VEC_PER_THREAD];
#pragma unroll
    for (int i = 0; i < VEC_PER_THREAD; i++)
        v[i] = xr[i * NTHREADS + t];

    __shared__ float s_xtrue;
    // The thread owning column `lab` publishes x_true from its registers.
    {
        int lv = lab >> 2;                 // float4 index
        int owner_t = lv & (NTHREADS - 1);
        int owner_i = lv >> 9;             // / NTHREADS
        if (t == owner_t) {
            float4 vv = v[owner_i];
            int c = lab & 3;
            s_xtrue = (c == 0) ? vv.x : (c == 1) ? vv.y : (c == 2) ? vv.z : vv.w;
        }
    }

    // Local max + argmax (first occurrence: columns ascend in i then j for fixed t).
    float m = -3.4e38f;
    int   idx = 0x7fffffff;
#pragma unroll
    for (int i = 0; i < VEC_PER_THREAD; i++) {
        int base = (i * NTHREADS + t) * 4;
        if (v[i].x > m) { m = v[i].x; idx = base;     }
        if (v[i].y > m) { m = v[i].y; idx = base + 1; }
        if (v[i].z > m) { m = v[i].z; idx = base + 2; }
        if (v[i].w > m) { m = v[i].w; idx = base + 3; }
    }

    // Local exp-sum against local max.
    float s = 0.f;
#pragma unroll
    for (int i = 0; i < VEC_PER_THREAD; i++) {
        s += __expf(v[i].x - m);
        s += __expf(v[i].y - m);
        s += __expf(v[i].z - m);
        s += __expf(v[i].w - m);
    }

    // Warp butterfly merge of (m, s, idx) with first-index tie-break.
#pragma unroll
    for (int off = 16; off > 0; off >>= 1) {
        float m2 = __shfl_xor_sync(0xffffffffu, m, off);
        float s2 = __shfl_xor_sync(0xffffffffu, s, off);
        int   i2 = __shfl_xor_sync(0xffffffffu, idx, off);
        float M  = fmaxf(m, m2);
        s = s * __expf(m - M) + s2 * __expf(m2 - M);
        if (m2 > m || (m2 == m && i2 < idx)) idx = i2;
        m = M;
    }

    // Cross-warp merge (16 warps) via shared memory; warp 0 finishes.
    __shared__ float sm[16], ss[16];
    __shared__ int   si[16];
    const int warp = t >> 5, lane = t & 31;
    if (lane == 0) { sm[warp] = m; ss[warp] = s; si[warp] = idx; }
    __syncthreads();
    if (warp == 0) {
        m   = (lane < 16) ? sm[lane] : -3.4e38f;
        s   = (lane < 16) ? ss[lane] : 0.f;
        idx = (lane < 16) ? si[lane] : 0x7fffffff;
#pragma unroll
        for (int off = 16; off > 0; off >>= 1) {
            float m2 = __shfl_xor_sync(0xffffffffu, m, off);
            float s2 = __shfl_xor_sync(0xffffffffu, s, off);
            int   i2 = __shfl_xor_sync(0xffffffffu, idx, off);
            float M  = fmaxf(m, m2);
            s = s * __expf(m - M) + s2 * __expf(m2 - M);
            if (m2 > m || (m2 == m && i2 < idx)) idx = i2;
            m = M;
        }
        if (lane == 0) {
            float lse = m + __logf(s);
            float p   = __expf(s_xtrue - lse);           // softmax prob of true class
            g_pen[row] = -__logf(p + 1e-7f) * (1.f - p); // base penalty (w=1)
            atomicAdd(&g_counts[idx], 1);
        }
    }
}

// Weight-multiply + deterministic tree reduction (no exp/log chains).
// is_tail computed from the label directly (tail_mask = arange(C) >= C-16 by
// construction). Re-zeroes g_counts after use for the next graph replay.
__global__ __launch_bounds__(1024) void finalize_kernel(
    const int* __restrict__ labels,
    const int* __restrict__ prev,
    float* __restrict__ out)
{
    const int t = threadIdx.x;
    float acc = 0.f;
    const int4*   lab4 = reinterpret_cast<const int4*>(labels);
    const float4* pen4 = reinterpret_cast<const float4*>(g_pen);
    for (int i = t; i < BB / 4; i += 1024) {
        float4 p4 = pen4[i];
        int4   l4 = lab4[i];
        int   labs[4] = {l4.x, l4.y, l4.z, l4.w};
        float pens[4] = {p4.x, p4.y, p4.z, p4.w};
#pragma unroll
        for (int k = 0; k < 4; k++) {
            int lb = clamp_lab(labs[k]);
            float w = 1.f;
            if (lb >= CC - NUM_TAIL) {
                int pv = prev[lb];
                int cu = g_counts[lb];
                if      (pv > 0 && cu < pv) w = 4.f;
                else if (pv > 0 && cu > pv) w = 2.f;
                else                        w = 3.f;
            }
            acc += pens[k] * w;
        }
    }
    __shared__ float red[32];
#pragma unroll
    for (int off = 16; off > 0; off >>= 1)
        acc += __shfl_xor_sync(0xffffffffu, acc, off);
    if ((t & 31) == 0) red[t >> 5] = acc;
    __syncthreads();   // all g_counts reads done — safe to re-zero below

    for (int i = t; i < CC; i += 1024) g_counts[i] = 0;

    if (t < 32) {
        acc = red[t];
#pragma unroll
        for (int off = 16; off > 0; off >>= 1)
            acc += __shfl_xor_sync(0xffffffffu, acc, off);
        if (t == 0) out[0] = acc * (0.1f / (float)BB);
    }
}

extern "C" void kernel_launch(void* const* d_in, const int* in_sizes, int n_in,
                              void* d_out, int out_size)
{
    const float* x      = (const float*)d_in[0];
    const int*   labels = (const int*)d_in[1];
    const int*   prev   = (const int*)d_in[2];
    float*       out    = (float*)d_out;

    row_kernel<<<BB, NTHREADS>>>(x, labels);
    finalize_kernel<<<1, 1024>>>(labels, prev, out);
}